// round 7
// baseline (speedup 1.0000x reference)
#include <cuda_runtime.h>
#include <cuda_fp16.h>
#include <cstdint>

// ---------------- problem constants ----------------
#define B_    8
#define T_    2048
#define DIM_  1024
#define E_    2048
#define M_TOT (B_ * T_)   // 16384 rows for all GEMMs

// ---------------- scratch (no allocs allowed) ----------------
static __device__ __half g_xh   [(size_t)M_TOT * DIM_];  // half copies of MMA operands
static __device__ __half g_winh [(size_t)E_ * DIM_];
static __device__ __half g_wxh  [(size_t)E_ * E_];
static __device__ __half g_wouth[(size_t)DIM_ * E_];
static __device__ __half g_xproj[(size_t)M_TOT * E_];    // GEMM1 out (half)
static __device__ float  g_u    [(size_t)M_TOT * E_];    // GEMM2 out (fp32, scan input)
static __device__ __half g_outs [(size_t)M_TOT * E_];    // scan out (half, GEMM3 input)

// ---------------- helpers ----------------
__device__ __forceinline__ uint32_t smem_to_u32(const void* p) {
    uint32_t a;
    asm("{ .reg .u64 t; cvta.to.shared.u64 t, %1; cvt.u32.u64 %0, t; }" : "=r"(a) : "l"(p));
    return a;
}

__device__ __forceinline__ void cp16(void* s, const void* g) {
    asm volatile("cp.async.cg.shared.global [%0], [%1], 16;"
                 :: "r"(smem_to_u32(s)), "l"(g) : "memory");
}
#define CP_COMMIT() asm volatile("cp.async.commit_group;" ::: "memory")
#define CP_WAIT1()  asm volatile("cp.async.wait_group 1;" ::: "memory")

// fp16 mma: D(16x8,f32) += A(16x16,f16) * B(16x8,f16)
__device__ __forceinline__ void mma_f16(float* c, const uint32_t* a, const uint32_t* b) {
    asm volatile(
        "mma.sync.aligned.m16n8k16.row.col.f32.f16.f16.f32 "
        "{%0,%1,%2,%3}, {%4,%5,%6,%7}, {%8,%9}, {%0,%1,%2,%3};"
        : "+f"(c[0]), "+f"(c[1]), "+f"(c[2]), "+f"(c[3])
        : "r"(a[0]), "r"(a[1]), "r"(a[2]), "r"(a[3]), "r"(b[0]), "r"(b[1]));
}

__device__ __forceinline__ void ldsm_x4(uint32_t* r, uint32_t addr) {
    asm volatile("ldmatrix.sync.aligned.m8n8.x4.shared.b16 {%0,%1,%2,%3}, [%4];"
        : "=r"(r[0]), "=r"(r[1]), "=r"(r[2]), "=r"(r[3]) : "r"(addr));
}

// ---------------- GEMM config ----------------
#define BM 128
#define BN 128
#define BK 64
#define SROW 72                         // padded row stride in halves (144B): ldmatrix conflict-free
#define TILE_HALVES (BM * SROW)         // one operand tile
#define STAGE_HALVES (2 * TILE_HALVES)  // A tile then B tile
#define STAGES 3
#define SMEM_BYTES (STAGES * STAGE_HALVES * 2)

// C[m,n] = sum_k A[m,k] * Bw[n,k]
// MODE 0: silu -> half C.  MODE 1: +bias -> float C.  MODE 2: identity -> float C.
template<int MODE>
__global__ void __launch_bounds__(128, 2)
gemm_fp16(const __half* __restrict__ A, const __half* __restrict__ Bw,
          const float* __restrict__ bias, void* __restrict__ Cout,
          int Ktot, int Ntot)
{
    extern __shared__ __align__(16) __half smem[];

    const int tid  = threadIdx.x;
    const int wid  = tid >> 5;
    const int lane = tid & 31;
    const int m0 = blockIdx.y * BM;
    const int n0 = blockIdx.x * BN;
    const int KT = Ktot / BK;

    // cp.async thread map: 16B (8-half) chunks; 8 chunks per 128B row
    const int lr = tid >> 3;          // 0..15
    const int lc = (tid & 7) * 8;     // half col 0,8,...,56

    auto load_stage = [&](int kt, int buf) {
        __half* sA = smem + buf * STAGE_HALVES;
        __half* sB = sA + TILE_HALVES;
        const int k0 = kt * BK;
#pragma unroll
        for (int p = 0; p < 8; ++p) {
            const int row = p * 16 + lr;
            cp16(&sA[row * SROW + lc], &A [(size_t)(m0 + row) * Ktot + k0 + lc]);
            cp16(&sB[row * SROW + lc], &Bw[(size_t)(n0 + row) * Ktot + k0 + lc]);
        }
    };

    // warp grid 2x2, warp tile 64x64
    const int wm = (wid >> 1) * 64;
    const int wn = (wid & 1) * 64;
    const int qr = lane >> 2;         // 0..7
    const int qc = lane & 3;          // 0..3

    // ldmatrix per-lane addressing: sel = which 8x8 matrix this lane's address feeds
    const int sel   = lane >> 3;      // 0..3
    const int lrow8 = lane & 7;       // row within the 8x8 matrix
    const uint32_t smem_base = smem_to_u32(smem);

    float acc[4][8][4];
#pragma unroll
    for (int mt = 0; mt < 4; ++mt)
#pragma unroll
        for (int nt = 0; nt < 8; ++nt)
#pragma unroll
            for (int i = 0; i < 4; ++i) acc[mt][nt][i] = 0.0f;

    auto compute = [&](int buf) {
        const uint32_t sA = smem_base + buf * (STAGE_HALVES * 2);
        const uint32_t sB = sA + TILE_HALVES * 2;
        // A matrices order: m0=(rows,k0) m1=(rows+8,k0) m2=(rows,k0+8) m3=(rows+8,k0+8)
        uint32_t aaddr[4], baddr[4];
#pragma unroll
        for (int mt = 0; mt < 4; ++mt)
            aaddr[mt] = sA + ((wm + mt * 16 + (sel & 1) * 8 + lrow8) * SROW + (sel >> 1) * 8) * 2;
        // B matrices order for pair p: m0=(nt0,k0) m1=(nt0,k0+8) m2=(nt1,k0) m3=(nt1,k0+8)
#pragma unroll
        for (int p = 0; p < 4; ++p)
            baddr[p] = sB + ((wn + (2 * p + (sel >> 1)) * 8 + lrow8) * SROW + (sel & 1) * 8) * 2;
#pragma unroll
        for (int ks = 0; ks < 4; ++ks) {          // 4 steps of k=16
            const uint32_t koff = ks * 32;        // 16 halves = 32 bytes
            uint32_t af[4][4];
#pragma unroll
            for (int mt = 0; mt < 4; ++mt)
                ldsm_x4(af[mt], aaddr[mt] + koff);
            uint32_t bf[8][2];
#pragma unroll
            for (int p = 0; p < 4; ++p) {
                uint32_t tmp[4];
                ldsm_x4(tmp, baddr[p] + koff);
                bf[2 * p][0]     = tmp[0];
                bf[2 * p][1]     = tmp[1];
                bf[2 * p + 1][0] = tmp[2];
                bf[2 * p + 1][1] = tmp[3];
            }
#pragma unroll
            for (int mt = 0; mt < 4; ++mt)
#pragma unroll
                for (int nt = 0; nt < 8; ++nt)
                    mma_f16(acc[mt][nt], af[mt], bf[nt]);
        }
    };

    // ---- pipelined mainloop (3-stage cp.async) ----
    load_stage(0, 0); CP_COMMIT();
    load_stage(1, 1); CP_COMMIT();
#pragma unroll 1
    for (int kt = 0; kt < KT; ++kt) {
        CP_WAIT1();
        __syncthreads();
        const int nk = kt + 2;
        if (nk < KT) load_stage(nk, nk % STAGES);
        CP_COMMIT();
        compute(kt % STAGES);
    }

    // ---- epilogue ----
#pragma unroll
    for (int mt = 0; mt < 4; ++mt) {
        const int row0 = m0 + wm + mt * 16 + qr;
#pragma unroll
        for (int nt = 0; nt < 8; ++nt) {
            const int col0 = n0 + wn + nt * 8 + 2 * qc;
            float v0 = acc[mt][nt][0], v1 = acc[mt][nt][1];
            float v2 = acc[mt][nt][2], v3 = acc[mt][nt][3];
            if (MODE == 0) {
                // silu, store half
                v0 = v0 * __fdividef(1.0f, 1.0f + __expf(-v0));
                v1 = v1 * __fdividef(1.0f, 1.0f + __expf(-v1));
                v2 = v2 * __fdividef(1.0f, 1.0f + __expf(-v2));
                v3 = v3 * __fdividef(1.0f, 1.0f + __expf(-v3));
                __half* C = (__half*)Cout;
                *reinterpret_cast<__half2*>(&C[(size_t)row0 * Ntot + col0]) =
                    __halves2half2(__float2half_rn(v0), __float2half_rn(v1));
                *reinterpret_cast<__half2*>(&C[(size_t)(row0 + 8) * Ntot + col0]) =
                    __halves2half2(__float2half_rn(v2), __float2half_rn(v3));
            } else {
                if (MODE == 1) {
                    const float b0 = bias[col0], b1 = bias[col0 + 1];
                    v0 += b0; v1 += b1; v2 += b0; v3 += b1;
                }
                float* C = (float*)Cout;
                *reinterpret_cast<float2*>(&C[(size_t)row0 * Ntot + col0])       = make_float2(v0, v1);
                *reinterpret_cast<float2*>(&C[(size_t)(row0 + 8) * Ntot + col0]) = make_float2(v2, v3);
            }
        }
    }
}

// ---------------- float -> half convert ----------------
__global__ void __launch_bounds__(256)
f2h_copy(const float* __restrict__ src, __half* __restrict__ dst, int n4)
{
    const int i = blockIdx.x * blockDim.x + threadIdx.x;
    if (i < n4) {
        float4 v = reinterpret_cast<const float4*>(src)[i];
        __half2 h0 = __floats2half2_rn(v.x, v.y);
        __half2 h1 = __floats2half2_rn(v.z, v.w);
        uint2 pk;
        pk.x = *reinterpret_cast<uint32_t*>(&h0);
        pk.y = *reinterpret_cast<uint32_t*>(&h1);
        *reinterpret_cast<uint2*>(&dst[(size_t)i * 4]) = pk;
    }
}

// ---------------- sequential scan: h = tanh(u + d*h); out = h * silu(h) ----------------
// tanh chain folded: e2 = 2^(c1*h + c0_t), c1 = -2*d*log2e (const), c0_t = -2*log2e*u_t
__global__ void __launch_bounds__(128)
scan_kernel(const float* __restrict__ U, const float* __restrict__ h0,
            const float* __restrict__ dvec, __half* __restrict__ outs,
            float* __restrict__ hfin)
{
    const int id = blockIdx.x * blockDim.x + threadIdx.x;   // 0 .. B*E-1
    const int b = id / E_;
    const int e = id - b * E_;
    const float LOG2E = 1.4426950408889634f;
    const float dc = fminf(fmaxf(dvec[e], -0.99f), 0.99f);
    const float c1 = -2.0f * LOG2E * dc;
    float h = h0[id];
    const size_t base = (size_t)b * T_ * E_ + e;
#pragma unroll 4
    for (int t = 0; t < T_; ++t) {
        const float uv = __ldcs(&U[base + (size_t)t * E_]);   // streaming, touch-once
        const float c0 = -2.0f * LOG2E * uv;      // off the critical path
        float e2, r;
        asm("ex2.approx.f32 %0, %1;" : "=f"(e2) : "f"(fmaf(c1, h, c0)));
        asm("rcp.approx.f32 %0, %1;" : "=f"(r) : "f"(1.0f + e2));
        h = fmaf(2.0f, r, -1.0f);                 // tanh(u + d*h)
        // out = h * silu(h) = h^2 * sigmoid(h)  (off the critical path)
        float eh, sr;
        asm("ex2.approx.f32 %0, %1;" : "=f"(eh) : "f"(-LOG2E * h));
        asm("rcp.approx.f32 %0, %1;" : "=f"(sr) : "f"(1.0f + eh));
        const __half hv = __float2half_rn(h * h * sr);
        __stcs(&outs[base + (size_t)t * E_], hv);             // streaming store
    }
    hfin[id] = h;
}

// ---------------- launcher ----------------
extern "C" void kernel_launch(void* const* d_in, const int* in_sizes, int n_in,
                              void* d_out, int out_size)
{
    const float* x     = (const float*)d_in[0];
    const float* h0    = (const float*)d_in[1];
    const float* W_in  = (const float*)d_in[2];
    const float* W_x   = (const float*)d_in[3];
    const float* dvec  = (const float*)d_in[4];
    const float* bias  = (const float*)d_in[5];
    const float* W_out = (const float*)d_in[6];
    float* out = (float*)d_out;

    __half *xh, *winh, *wxh, *wouth, *xproj, *outs;
    float *u;
    cudaGetSymbolAddress((void**)&xh,    g_xh);
    cudaGetSymbolAddress((void**)&winh,  g_winh);
    cudaGetSymbolAddress((void**)&wxh,   g_wxh);
    cudaGetSymbolAddress((void**)&wouth, g_wouth);
    cudaGetSymbolAddress((void**)&xproj, g_xproj);
    cudaGetSymbolAddress((void**)&u,     g_u);
    cudaGetSymbolAddress((void**)&outs,  g_outs);

    cudaFuncSetAttribute(gemm_fp16<0>, cudaFuncAttributeMaxDynamicSharedMemorySize, SMEM_BYTES);
    cudaFuncSetAttribute(gemm_fp16<1>, cudaFuncAttributeMaxDynamicSharedMemorySize, SMEM_BYTES);
    cudaFuncSetAttribute(gemm_fp16<2>, cudaFuncAttributeMaxDynamicSharedMemorySize, SMEM_BYTES);

    // convert MMA operands to half once
    {
        int n4;
        n4 = (M_TOT * DIM_) / 4; f2h_copy<<<(n4 + 255) / 256, 256>>>(x, xh, n4);
        n4 = (E_ * DIM_) / 4;    f2h_copy<<<(n4 + 255) / 256, 256>>>(W_in, winh, n4);
        n4 = (E_ * E_) / 4;      f2h_copy<<<(n4 + 255) / 256, 256>>>(W_x, wxh, n4);
        n4 = (DIM_ * E_) / 4;    f2h_copy<<<(n4 + 255) / 256, 256>>>(W_out, wouth, n4);
    }

    // GEMM1: x @ W_in^T -> silu -> xproj (half)
    gemm_fp16<0><<<dim3(E_ / BN, M_TOT / BM), 128, SMEM_BYTES>>>(xh, winh, nullptr, xproj, DIM_, E_);
    // GEMM2: xproj @ W_x^T + b -> u (fp32)
    gemm_fp16<1><<<dim3(E_ / BN, M_TOT / BM), 128, SMEM_BYTES>>>(xproj, wxh, bias, u, E_, E_);
    // scan over T; outs half; h_final appended after output
    scan_kernel<<<(B_ * E_) / 128, 128>>>(u, h0, dvec, outs, out + (size_t)M_TOT * DIM_);
    // GEMM3: outs @ W_out^T -> output (fp32)
    gemm_fp16<2><<<dim3(DIM_ / BN, M_TOT / BM), 128, SMEM_BYTES>>>(outs, wouth, nullptr, out, E_, DIM_);
}

// round 9
// speedup vs baseline: 1.4334x; 1.4334x over previous
#include <cuda_runtime.h>
#include <cuda_fp16.h>
#include <cstdint>

// ---------------- problem constants ----------------
#define B_    8
#define T_    2048
#define DIM_  1024
#define E_    2048
#define M_TOT (B_ * T_)   // 16384 rows for all GEMMs

// ---------------- scratch (no allocs allowed) ----------------
static __device__ __half g_xh   [(size_t)M_TOT * DIM_];  // half copies of MMA operands
static __device__ __half g_winh [(size_t)E_ * DIM_];
static __device__ __half g_wxh  [(size_t)E_ * E_];
static __device__ __half g_wouth[(size_t)DIM_ * E_];
static __device__ __half g_xproj[(size_t)M_TOT * E_];    // GEMM1 out (half)
static __device__ float  g_u    [(size_t)M_TOT * E_];    // GEMM2 out (fp32, scan input)
static __device__ __half g_outs [(size_t)M_TOT * E_];    // scan out (half, GEMM3 input)

// ---------------- helpers ----------------
__device__ __forceinline__ uint32_t smem_to_u32(const void* p) {
    uint32_t a;
    asm("{ .reg .u64 t; cvta.to.shared.u64 t, %1; cvt.u32.u64 %0, t; }" : "=r"(a) : "l"(p));
    return a;
}

__device__ __forceinline__ void cp16(void* s, const void* g) {
    asm volatile("cp.async.cg.shared.global [%0], [%1], 16;"
                 :: "r"(smem_to_u32(s)), "l"(g) : "memory");
}
#define CP_COMMIT() asm volatile("cp.async.commit_group;" ::: "memory")
#define CP_WAIT1()  asm volatile("cp.async.wait_group 1;" ::: "memory")

// fp16 mma: D(16x8,f32) += A(16x16,f16) * B(16x8,f16)
__device__ __forceinline__ void mma_f16(float* c, const uint32_t* a, const uint32_t* b) {
    asm volatile(
        "mma.sync.aligned.m16n8k16.row.col.f32.f16.f16.f32 "
        "{%0,%1,%2,%3}, {%4,%5,%6,%7}, {%8,%9}, {%0,%1,%2,%3};"
        : "+f"(c[0]), "+f"(c[1]), "+f"(c[2]), "+f"(c[3])
        : "r"(a[0]), "r"(a[1]), "r"(a[2]), "r"(a[3]), "r"(b[0]), "r"(b[1]));
}

// ---------------- GEMM config ----------------
// CTA tile 256x128 (BM x BN), BK=64.  8 warps (256 thr), warp tile 64x64 (4x2 grid).
// L2 traffic: (256+128)*64*2 = 48KB per slab for 2M MACs = 0.023 B/MAC (was 0.031).
#define BM 256
#define BN 128
#define BK 64
#define SROW 72                         // padded row stride in halves (144B, 16B mult.)
#define A_HALVES (BM * SROW)
#define B_HALVES (BN * SROW)
#define STAGE_HALVES (A_HALVES + B_HALVES)
#define STAGES 3
#define SMEM_BYTES (STAGES * STAGE_HALVES * 2)   // 165888 B

// C[m,n] = sum_k A[m,k] * Bw[n,k]
// MODE 0: silu -> half C.  MODE 1: +bias -> float C.  MODE 2: identity -> float C.
template<int MODE>
__global__ void __launch_bounds__(256, 1)
gemm_fp16(const __half* __restrict__ A, const __half* __restrict__ Bw,
          const float* __restrict__ bias, void* __restrict__ Cout,
          int Ktot, int Ntot)
{
    extern __shared__ __align__(16) __half smem[];

    const int tid  = threadIdx.x;
    const int wid  = tid >> 5;
    const int lane = tid & 31;
    const int m0 = blockIdx.y * BM;
    const int n0 = blockIdx.x * BN;
    const int KT = Ktot / BK;

    // cp.async thread map: 16B (8-half) chunks; 8 chunks per 128B row; 256 threads
    const int lr = tid >> 3;          // 0..31
    const int lc = (tid & 7) * 8;     // half col 0,8,...,56

    auto load_stage = [&](int kt, int buf) {
        __half* sA = smem + buf * STAGE_HALVES;
        __half* sB = sA + A_HALVES;
        const int k0 = kt * BK;
#pragma unroll
        for (int p = 0; p < 8; ++p) {     // A: 8 passes x 32 rows = 256 rows
            const int row = p * 32 + lr;
            cp16(&sA[row * SROW + lc], &A[(size_t)(m0 + row) * Ktot + k0 + lc]);
        }
#pragma unroll
        for (int p = 0; p < 4; ++p) {     // B: 4 passes x 32 rows = 128 rows
            const int row = p * 32 + lr;
            cp16(&sB[row * SROW + lc], &Bw[(size_t)(n0 + row) * Ktot + k0 + lc]);
        }
    };

    // warp grid 4(m) x 2(n), warp tile 64x64
    const int wm = (wid >> 1) * 64;
    const int wn = (wid & 1) * 64;
    const int qr = lane >> 2;         // 0..7
    const int qc = lane & 3;          // 0..3

    float acc[4][8][4];
#pragma unroll
    for (int mt = 0; mt < 4; ++mt)
#pragma unroll
        for (int nt = 0; nt < 8; ++nt)
#pragma unroll
            for (int i = 0; i < 4; ++i) acc[mt][nt][i] = 0.0f;

    auto compute = [&](int buf) {
        const __half* sA = smem + buf * STAGE_HALVES;
        const __half* sB = sA + A_HALVES;
#pragma unroll
        for (int ks = 0; ks < 4; ++ks) {          // 4 steps of k=16
            const int k0 = ks * 16;
            uint32_t af[4][4];
#pragma unroll
            for (int mt = 0; mt < 4; ++mt) {
                const int base = (wm + mt * 16 + qr) * SROW + k0 + qc * 2;
                af[mt][0] = *reinterpret_cast<const uint32_t*>(&sA[base]);
                af[mt][1] = *reinterpret_cast<const uint32_t*>(&sA[base + 8 * SROW]);
                af[mt][2] = *reinterpret_cast<const uint32_t*>(&sA[base + 8]);
                af[mt][3] = *reinterpret_cast<const uint32_t*>(&sA[base + 8 * SROW + 8]);
            }
            uint32_t bf[8][2];
#pragma unroll
            for (int nt = 0; nt < 8; ++nt) {
                const int base = (wn + nt * 8 + qr) * SROW + k0 + qc * 2;
                bf[nt][0] = *reinterpret_cast<const uint32_t*>(&sB[base]);
                bf[nt][1] = *reinterpret_cast<const uint32_t*>(&sB[base + 8]);
            }
#pragma unroll
            for (int mt = 0; mt < 4; ++mt)
#pragma unroll
                for (int nt = 0; nt < 8; ++nt)
                    mma_f16(acc[mt][nt], af[mt], bf[nt]);
        }
    };

    // ---- pipelined mainloop (3-stage cp.async) ----
    load_stage(0, 0); CP_COMMIT();
    load_stage(1, 1); CP_COMMIT();
#pragma unroll 1
    for (int kt = 0; kt < KT; ++kt) {
        CP_WAIT1();
        __syncthreads();
        const int nk = kt + 2;
        if (nk < KT) load_stage(nk, nk % STAGES);
        CP_COMMIT();
        compute(kt % STAGES);
    }

    // ---- epilogue ----
#pragma unroll
    for (int mt = 0; mt < 4; ++mt) {
        const int row0 = m0 + wm + mt * 16 + qr;
#pragma unroll
        for (int nt = 0; nt < 8; ++nt) {
            const int col0 = n0 + wn + nt * 8 + 2 * qc;
            float v0 = acc[mt][nt][0], v1 = acc[mt][nt][1];
            float v2 = acc[mt][nt][2], v3 = acc[mt][nt][3];
            if (MODE == 0) {
                // silu, store half
                v0 = v0 * __fdividef(1.0f, 1.0f + __expf(-v0));
                v1 = v1 * __fdividef(1.0f, 1.0f + __expf(-v1));
                v2 = v2 * __fdividef(1.0f, 1.0f + __expf(-v2));
                v3 = v3 * __fdividef(1.0f, 1.0f + __expf(-v3));
                __half* C = (__half*)Cout;
                *reinterpret_cast<__half2*>(&C[(size_t)row0 * Ntot + col0]) =
                    __halves2half2(__float2half_rn(v0), __float2half_rn(v1));
                *reinterpret_cast<__half2*>(&C[(size_t)(row0 + 8) * Ntot + col0]) =
                    __halves2half2(__float2half_rn(v2), __float2half_rn(v3));
            } else {
                if (MODE == 1) {
                    const float b0 = bias[col0], b1 = bias[col0 + 1];
                    v0 += b0; v1 += b1; v2 += b0; v3 += b1;
                }
                float* C = (float*)Cout;
                *reinterpret_cast<float2*>(&C[(size_t)row0 * Ntot + col0])       = make_float2(v0, v1);
                *reinterpret_cast<float2*>(&C[(size_t)(row0 + 8) * Ntot + col0]) = make_float2(v2, v3);
            }
        }
    }
}

// ---------------- float -> half convert ----------------
__global__ void __launch_bounds__(256)
f2h_copy(const float* __restrict__ src, __half* __restrict__ dst, int n4)
{
    const int i = blockIdx.x * blockDim.x + threadIdx.x;
    if (i < n4) {
        float4 v = reinterpret_cast<const float4*>(src)[i];
        __half2 h0 = __floats2half2_rn(v.x, v.y);
        __half2 h1 = __floats2half2_rn(v.z, v.w);
        uint2 pk;
        pk.x = *reinterpret_cast<uint32_t*>(&h0);
        pk.y = *reinterpret_cast<uint32_t*>(&h1);
        *reinterpret_cast<uint2*>(&dst[(size_t)i * 4]) = pk;
    }
}

// ---------------- sequential scan: h = tanh(u + d*h); out = h * silu(h) ----------------
// tanh chain folded: e2 = 2^(c1*h + c0_t), c1 = -2*d*log2e (const), c0_t = -2*log2e*u_t
__global__ void __launch_bounds__(128)
scan_kernel(const float* __restrict__ U, const float* __restrict__ h0,
            const float* __restrict__ dvec, __half* __restrict__ outs,
            float* __restrict__ hfin)
{
    const int id = blockIdx.x * blockDim.x + threadIdx.x;   // 0 .. B*E-1
    const int b = id / E_;
    const int e = id - b * E_;
    const float LOG2E = 1.4426950408889634f;
    const float dc = fminf(fmaxf(dvec[e], -0.99f), 0.99f);
    const float c1 = -2.0f * LOG2E * dc;
    float h = h0[id];
    const size_t base = (size_t)b * T_ * E_ + e;
#pragma unroll 4
    for (int t = 0; t < T_; ++t) {
        const float uv = U[base + (size_t)t * E_];
        const float c0 = -2.0f * LOG2E * uv;      // off the critical path
        float e2, r;
        asm("ex2.approx.f32 %0, %1;" : "=f"(e2) : "f"(fmaf(c1, h, c0)));
        asm("rcp.approx.f32 %0, %1;" : "=f"(r) : "f"(1.0f + e2));
        h = fmaf(2.0f, r, -1.0f);                 // tanh(u + d*h)
        // out = h * silu(h) = h^2 * sigmoid(h)  (off the critical path)
        float eh, sr;
        asm("ex2.approx.f32 %0, %1;" : "=f"(eh) : "f"(-LOG2E * h));
        asm("rcp.approx.f32 %0, %1;" : "=f"(sr) : "f"(1.0f + eh));
        outs[base + (size_t)t * E_] = __float2half_rn(h * h * sr);
    }
    hfin[id] = h;
}

// ---------------- launcher ----------------
extern "C" void kernel_launch(void* const* d_in, const int* in_sizes, int n_in,
                              void* d_out, int out_size)
{
    const float* x     = (const float*)d_in[0];
    const float* h0    = (const float*)d_in[1];
    const float* W_in  = (const float*)d_in[2];
    const float* W_x   = (const float*)d_in[3];
    const float* dvec  = (const float*)d_in[4];
    const float* bias  = (const float*)d_in[5];
    const float* W_out = (const float*)d_in[6];
    float* out = (float*)d_out;

    __half *xh, *winh, *wxh, *wouth, *xproj, *outs;
    float *u;
    cudaGetSymbolAddress((void**)&xh,    g_xh);
    cudaGetSymbolAddress((void**)&winh,  g_winh);
    cudaGetSymbolAddress((void**)&wxh,   g_wxh);
    cudaGetSymbolAddress((void**)&wouth, g_wouth);
    cudaGetSymbolAddress((void**)&xproj, g_xproj);
    cudaGetSymbolAddress((void**)&u,     g_u);
    cudaGetSymbolAddress((void**)&outs,  g_outs);

    cudaFuncSetAttribute(gemm_fp16<0>, cudaFuncAttributeMaxDynamicSharedMemorySize, SMEM_BYTES);
    cudaFuncSetAttribute(gemm_fp16<1>, cudaFuncAttributeMaxDynamicSharedMemorySize, SMEM_BYTES);
    cudaFuncSetAttribute(gemm_fp16<2>, cudaFuncAttributeMaxDynamicSharedMemorySize, SMEM_BYTES);

    // convert MMA operands to half once
    {
        int n4;
        n4 = (M_TOT * DIM_) / 4; f2h_copy<<<(n4 + 255) / 256, 256>>>(x, xh, n4);
        n4 = (E_ * DIM_) / 4;    f2h_copy<<<(n4 + 255) / 256, 256>>>(W_in, winh, n4);
        n4 = (E_ * E_) / 4;      f2h_copy<<<(n4 + 255) / 256, 256>>>(W_x, wxh, n4);
        n4 = (DIM_ * E_) / 4;    f2h_copy<<<(n4 + 255) / 256, 256>>>(W_out, wouth, n4);
    }

    // GEMM1: x @ W_in^T -> silu -> xproj (half)
    gemm_fp16<0><<<dim3(E_ / BN, M_TOT / BM), 256, SMEM_BYTES>>>(xh, winh, nullptr, xproj, DIM_, E_);
    // GEMM2: xproj @ W_x^T + b -> u (fp32)
    gemm_fp16<1><<<dim3(E_ / BN, M_TOT / BM), 256, SMEM_BYTES>>>(xproj, wxh, bias, u, E_, E_);
    // scan over T; outs half; h_final appended after output
    scan_kernel<<<(B_ * E_) / 128, 128>>>(u, h0, dvec, outs, out + (size_t)M_TOT * DIM_);
    // GEMM3: outs @ W_out^T -> output (fp32)
    gemm_fp16<2><<<dim3(DIM_ / BN, M_TOT / BM), 256, SMEM_BYTES>>>(outs, wouth, nullptr, out, E_, DIM_);
}

// round 10
// speedup vs baseline: 1.5046x; 1.0496x over previous
#include <cuda_runtime.h>
#include <cuda_fp16.h>
#include <cstdint>

// ---------------- problem constants ----------------
#define B_    8
#define T_    2048
#define DIM_  1024
#define E_    2048
#define M_TOT (B_ * T_)   // 16384 rows for all GEMMs

// ---------------- scratch (no allocs allowed) ----------------
static __device__ __half g_xh   [(size_t)M_TOT * DIM_];  // half copies of MMA operands
static __device__ __half g_winh [(size_t)E_ * DIM_];
static __device__ __half g_wxh  [(size_t)E_ * E_];
static __device__ __half g_wouth[(size_t)DIM_ * E_];
static __device__ __half g_xproj[(size_t)M_TOT * E_];    // GEMM1 out (half)
static __device__ __half g_u    [(size_t)M_TOT * E_];    // GEMM2 out (half, scan input)
static __device__ __half g_outs [(size_t)M_TOT * E_];    // scan out (half, GEMM3 input)

// ---------------- helpers ----------------
__device__ __forceinline__ uint32_t smem_to_u32(const void* p) {
    uint32_t a;
    asm("{ .reg .u64 t; cvta.to.shared.u64 t, %1; cvt.u32.u64 %0, t; }" : "=r"(a) : "l"(p));
    return a;
}

__device__ __forceinline__ void cp16(void* s, const void* g) {
    asm volatile("cp.async.cg.shared.global [%0], [%1], 16;"
                 :: "r"(smem_to_u32(s)), "l"(g) : "memory");
}
#define CP_COMMIT() asm volatile("cp.async.commit_group;" ::: "memory")
#define CP_WAIT1()  asm volatile("cp.async.wait_group 1;" ::: "memory")

// fp16 mma: D(16x8,f32) += A(16x16,f16) * B(16x8,f16)
__device__ __forceinline__ void mma_f16(float* c, const uint32_t* a, const uint32_t* b) {
    asm volatile(
        "mma.sync.aligned.m16n8k16.row.col.f32.f16.f16.f32 "
        "{%0,%1,%2,%3}, {%4,%5,%6,%7}, {%8,%9}, {%0,%1,%2,%3};"
        : "+f"(c[0]), "+f"(c[1]), "+f"(c[2]), "+f"(c[3])
        : "r"(a[0]), "r"(a[1]), "r"(a[2]), "r"(a[3]), "r"(b[0]), "r"(b[1]));
}

// ---------------- GEMM config (round-5 proven: 128x128, 2 CTAs/SM) ----------------
#define BM 128
#define BN 128
#define BK 64
#define SROW 72                         // padded row stride in halves (144B, 16B mult.)
#define TILE_HALVES (BM * SROW)         // one operand tile
#define STAGE_HALVES (2 * TILE_HALVES)  // A tile then B tile
#define STAGES 3
#define SMEM_BYTES (STAGES * STAGE_HALVES * 2)

// C[m,n] = sum_k A[m,k] * Bw[n,k]
// MODE 0: silu -> half C.  MODE 1: +bias -> half C.  MODE 2: identity -> float C.
template<int MODE>
__global__ void __launch_bounds__(128, 2)
gemm_fp16(const __half* __restrict__ A, const __half* __restrict__ Bw,
          const float* __restrict__ bias, void* __restrict__ Cout,
          int Ktot, int Ntot)
{
    extern __shared__ __align__(16) __half smem[];

    const int tid  = threadIdx.x;
    const int wid  = tid >> 5;
    const int lane = tid & 31;
    const int m0 = blockIdx.y * BM;
    const int n0 = blockIdx.x * BN;
    const int KT = Ktot / BK;

    // cp.async thread map: 16B (8-half) chunks; 8 chunks per 128B row
    const int lr = tid >> 3;          // 0..15
    const int lc = (tid & 7) * 8;     // half col 0,8,...,56

    auto load_stage = [&](int kt, int buf) {
        __half* sA = smem + buf * STAGE_HALVES;
        __half* sB = sA + TILE_HALVES;
        const int k0 = kt * BK;
#pragma unroll
        for (int p = 0; p < 8; ++p) {
            const int row = p * 16 + lr;
            cp16(&sA[row * SROW + lc], &A [(size_t)(m0 + row) * Ktot + k0 + lc]);
            cp16(&sB[row * SROW + lc], &Bw[(size_t)(n0 + row) * Ktot + k0 + lc]);
        }
    };

    // warp grid 2x2, warp tile 64x64
    const int wm = (wid >> 1) * 64;
    const int wn = (wid & 1) * 64;
    const int qr = lane >> 2;         // 0..7
    const int qc = lane & 3;          // 0..3

    float acc[4][8][4];
#pragma unroll
    for (int mt = 0; mt < 4; ++mt)
#pragma unroll
        for (int nt = 0; nt < 8; ++nt)
#pragma unroll
            for (int i = 0; i < 4; ++i) acc[mt][nt][i] = 0.0f;

    auto compute = [&](int buf) {
        const __half* sA = smem + buf * STAGE_HALVES;
        const __half* sB = sA + TILE_HALVES;
#pragma unroll
        for (int ks = 0; ks < 4; ++ks) {          // 4 steps of k=16
            const int k0 = ks * 16;
            uint32_t af[4][4];
#pragma unroll
            for (int mt = 0; mt < 4; ++mt) {
                const int base = (wm + mt * 16 + qr) * SROW + k0 + qc * 2;
                af[mt][0] = *reinterpret_cast<const uint32_t*>(&sA[base]);
                af[mt][1] = *reinterpret_cast<const uint32_t*>(&sA[base + 8 * SROW]);
                af[mt][2] = *reinterpret_cast<const uint32_t*>(&sA[base + 8]);
                af[mt][3] = *reinterpret_cast<const uint32_t*>(&sA[base + 8 * SROW + 8]);
            }
            uint32_t bf[8][2];
#pragma unroll
            for (int nt = 0; nt < 8; ++nt) {
                const int base = (wn + nt * 8 + qr) * SROW + k0 + qc * 2;
                bf[nt][0] = *reinterpret_cast<const uint32_t*>(&sB[base]);
                bf[nt][1] = *reinterpret_cast<const uint32_t*>(&sB[base + 8]);
            }
#pragma unroll
            for (int mt = 0; mt < 4; ++mt)
#pragma unroll
                for (int nt = 0; nt < 8; ++nt)
                    mma_f16(acc[mt][nt], af[mt], bf[nt]);
        }
    };

    // ---- pipelined mainloop (3-stage cp.async) ----
    load_stage(0, 0); CP_COMMIT();
    load_stage(1, 1); CP_COMMIT();
#pragma unroll 1
    for (int kt = 0; kt < KT; ++kt) {
        CP_WAIT1();
        __syncthreads();
        const int nk = kt + 2;
        if (nk < KT) load_stage(nk, nk % STAGES);
        CP_COMMIT();
        compute(kt % STAGES);
    }

    // ---- epilogue ----
#pragma unroll
    for (int mt = 0; mt < 4; ++mt) {
        const int row0 = m0 + wm + mt * 16 + qr;
#pragma unroll
        for (int nt = 0; nt < 8; ++nt) {
            const int col0 = n0 + wn + nt * 8 + 2 * qc;
            float v0 = acc[mt][nt][0], v1 = acc[mt][nt][1];
            float v2 = acc[mt][nt][2], v3 = acc[mt][nt][3];
            if (MODE == 0) {
                // silu, store half
                v0 = v0 * __fdividef(1.0f, 1.0f + __expf(-v0));
                v1 = v1 * __fdividef(1.0f, 1.0f + __expf(-v1));
                v2 = v2 * __fdividef(1.0f, 1.0f + __expf(-v2));
                v3 = v3 * __fdividef(1.0f, 1.0f + __expf(-v3));
            } else if (MODE == 1) {
                const float b0 = bias[col0], b1 = bias[col0 + 1];
                v0 += b0; v1 += b1; v2 += b0; v3 += b1;
            }
            if (MODE == 2) {
                float* C = (float*)Cout;
                *reinterpret_cast<float2*>(&C[(size_t)row0 * Ntot + col0])       = make_float2(v0, v1);
                *reinterpret_cast<float2*>(&C[(size_t)(row0 + 8) * Ntot + col0]) = make_float2(v2, v3);
            } else {
                __half* C = (__half*)Cout;
                *reinterpret_cast<__half2*>(&C[(size_t)row0 * Ntot + col0]) =
                    __halves2half2(__float2half_rn(v0), __float2half_rn(v1));
                *reinterpret_cast<__half2*>(&C[(size_t)(row0 + 8) * Ntot + col0]) =
                    __halves2half2(__float2half_rn(v2), __float2half_rn(v3));
            }
        }
    }
}

// ---------------- float -> half convert ----------------
__global__ void __launch_bounds__(256)
f2h_copy(const float* __restrict__ src, __half* __restrict__ dst, int n4)
{
    const int i = blockIdx.x * blockDim.x + threadIdx.x;
    if (i < n4) {
        float4 v = reinterpret_cast<const float4*>(src)[i];
        __half2 h0 = __floats2half2_rn(v.x, v.y);
        __half2 h1 = __floats2half2_rn(v.z, v.w);
        uint2 pk;
        pk.x = *reinterpret_cast<uint32_t*>(&h0);
        pk.y = *reinterpret_cast<uint32_t*>(&h1);
        *reinterpret_cast<uint2*>(&dst[(size_t)i * 4]) = pk;
    }
}

// ---------------- sequential scan: h = tanh(u + d*h); out = h * silu(h) ----------------
// tanh chain folded: e2 = 2^(c1*h + c0_t), c1 = -2*d*log2e (const), c0_t = -2*log2e*u_t
__global__ void __launch_bounds__(128)
scan_kernel(const __half* __restrict__ U, const float* __restrict__ h0,
            const float* __restrict__ dvec, __half* __restrict__ outs,
            float* __restrict__ hfin)
{
    const int id = blockIdx.x * blockDim.x + threadIdx.x;   // 0 .. B*E-1
    const int b = id / E_;
    const int e = id - b * E_;
    const float LOG2E = 1.4426950408889634f;
    const float dc = fminf(fmaxf(dvec[e], -0.99f), 0.99f);
    const float c1 = -2.0f * LOG2E * dc;
    float h = h0[id];
    const size_t base = (size_t)b * T_ * E_ + e;
#pragma unroll 4
    for (int t = 0; t < T_; ++t) {
        const float uv = __half2float(U[base + (size_t)t * E_]);
        const float c0 = -2.0f * LOG2E * uv;      // off the critical path
        float e2, r;
        asm("ex2.approx.f32 %0, %1;" : "=f"(e2) : "f"(fmaf(c1, h, c0)));
        asm("rcp.approx.f32 %0, %1;" : "=f"(r) : "f"(1.0f + e2));
        h = fmaf(2.0f, r, -1.0f);                 // tanh(u + d*h)
        // out = h * silu(h) = h^2 * sigmoid(h)  (off the critical path)
        float eh, sr;
        asm("ex2.approx.f32 %0, %1;" : "=f"(eh) : "f"(-LOG2E * h));
        asm("rcp.approx.f32 %0, %1;" : "=f"(sr) : "f"(1.0f + eh));
        outs[base + (size_t)t * E_] = __float2half_rn(h * h * sr);
    }
    hfin[id] = h;
}

// ---------------- launcher ----------------
extern "C" void kernel_launch(void* const* d_in, const int* in_sizes, int n_in,
                              void* d_out, int out_size)
{
    const float* x     = (const float*)d_in[0];
    const float* h0    = (const float*)d_in[1];
    const float* W_in  = (const float*)d_in[2];
    const float* W_x   = (const float*)d_in[3];
    const float* dvec  = (const float*)d_in[4];
    const float* bias  = (const float*)d_in[5];
    const float* W_out = (const float*)d_in[6];
    float* out = (float*)d_out;

    __half *xh, *winh, *wxh, *wouth, *xproj, *u, *outs;
    cudaGetSymbolAddress((void**)&xh,    g_xh);
    cudaGetSymbolAddress((void**)&winh,  g_winh);
    cudaGetSymbolAddress((void**)&wxh,   g_wxh);
    cudaGetSymbolAddress((void**)&wouth, g_wouth);
    cudaGetSymbolAddress((void**)&xproj, g_xproj);
    cudaGetSymbolAddress((void**)&u,     g_u);
    cudaGetSymbolAddress((void**)&outs,  g_outs);

    cudaFuncSetAttribute(gemm_fp16<0>, cudaFuncAttributeMaxDynamicSharedMemorySize, SMEM_BYTES);
    cudaFuncSetAttribute(gemm_fp16<1>, cudaFuncAttributeMaxDynamicSharedMemorySize, SMEM_BYTES);
    cudaFuncSetAttribute(gemm_fp16<2>, cudaFuncAttributeMaxDynamicSharedMemorySize, SMEM_BYTES);

    // convert MMA operands to half once
    {
        int n4;
        n4 = (M_TOT * DIM_) / 4; f2h_copy<<<(n4 + 255) / 256, 256>>>(x, xh, n4);
        n4 = (E_ * DIM_) / 4;    f2h_copy<<<(n4 + 255) / 256, 256>>>(W_in, winh, n4);
        n4 = (E_ * E_) / 4;      f2h_copy<<<(n4 + 255) / 256, 256>>>(W_x, wxh, n4);
        n4 = (DIM_ * E_) / 4;    f2h_copy<<<(n4 + 255) / 256, 256>>>(W_out, wouth, n4);
    }

    // GEMM1: x @ W_in^T -> silu -> xproj (half)
    gemm_fp16<0><<<dim3(E_ / BN, M_TOT / BM), 128, SMEM_BYTES>>>(xh, winh, nullptr, xproj, DIM_, E_);
    // GEMM2: xproj @ W_x^T + b -> u (half)
    gemm_fp16<1><<<dim3(E_ / BN, M_TOT / BM), 128, SMEM_BYTES>>>(xproj, wxh, bias, u, E_, E_);
    // scan over T; outs half; h_final appended after output
    scan_kernel<<<(B_ * E_) / 128, 128>>>(u, h0, dvec, outs, out + (size_t)M_TOT * DIM_);
    // GEMM3: outs @ W_out^T -> output (fp32)
    gemm_fp16<2><<<dim3(DIM_ / BN, M_TOT / BM), 128, SMEM_BYTES>>>(outs, wouth, nullptr, out, E_, DIM_);
}